// round 3
// baseline (speedup 1.0000x reference)
#include <cuda_runtime.h>
#include <math.h>
#include <float.h>

#define HID 1536
#define NH  8
#define HD  192
#define WW  12
#define CC  24
#define FF  13
#define MAXPAST 12

// Scratch (no-alloc rule: __device__ globals). 4*4096 rows x 1536 cols each.
__device__ float g_q[25165824];
__device__ float g_k[25165824];
__device__ float g_v[25165824];
__device__ float g_sin[FF * HID];   // projected sinusoid [F, HID]

// ---------------------------------------------------------------------------
// QKV GEMM: O = A @ W, A [M,K] row-major, W [K,N] row-major.
// 128x128 tile, BK=8, 256 threads, 8x8 per-thread, double-buffered smem.
// blockIdx.z in {0,1,2} selects (Wq->g_q, Wk->g_k, Wv->g_v).
// ---------------------------------------------------------------------------
__global__ __launch_bounds__(256) void qkv_gemm(
    const float* __restrict__ A,
    const float* __restrict__ Wq,
    const float* __restrict__ Wk,
    const float* __restrict__ Wv,
    int M, int K, int N)
{
    const float* Wt = (blockIdx.z == 0) ? Wq : (blockIdx.z == 1) ? Wk : Wv;
    float* O = (blockIdx.z == 0) ? g_q : (blockIdx.z == 1) ? g_k : g_v;

    __shared__ float As[2][8][128];
    __shared__ float Bs[2][8][128];

    const int tid  = threadIdx.x;
    const int arow = tid >> 1;          // 0..127
    const int acol = (tid & 1) << 2;    // 0 or 4
    const int brow = tid >> 5;          // 0..7
    const int bcol = (tid & 31) << 2;   // 0..124

    const float* Ap = A  + (size_t)(blockIdx.y * 128 + arow) * K + acol;
    const float* Bp = Wt + (size_t)brow * N + blockIdx.x * 128 + bcol;

    float4 a4 = *(const float4*)Ap;
    float4 b4 = *(const float4*)Bp;
    As[0][acol + 0][arow] = a4.x;
    As[0][acol + 1][arow] = a4.y;
    As[0][acol + 2][arow] = a4.z;
    As[0][acol + 3][arow] = a4.w;
    *(float4*)&Bs[0][brow][bcol] = b4;
    __syncthreads();

    float acc[8][8];
    #pragma unroll
    for (int i = 0; i < 8; i++)
        #pragma unroll
        for (int j = 0; j < 8; j++) acc[i][j] = 0.f;

    const int ty = tid >> 4;   // 0..15 (row group)
    const int tx = tid & 15;   // 0..15 (col group)
    const int nk = K >> 3;
    int cur = 0;

    for (int t = 0; t < nk; ++t) {
        if (t + 1 < nk) {
            a4 = *(const float4*)(Ap + (t + 1) * 8);
            b4 = *(const float4*)(Bp + (size_t)(t + 1) * 8 * N);
        }
        #pragma unroll
        for (int kk = 0; kk < 8; kk++) {
            float4 x0 = *(const float4*)&As[cur][kk][ty * 8];
            float4 x1 = *(const float4*)&As[cur][kk][ty * 8 + 4];
            float4 y0 = *(const float4*)&Bs[cur][kk][tx * 8];
            float4 y1 = *(const float4*)&Bs[cur][kk][tx * 8 + 4];
            float ar[8] = {x0.x, x0.y, x0.z, x0.w, x1.x, x1.y, x1.z, x1.w};
            float br[8] = {y0.x, y0.y, y0.z, y0.w, y1.x, y1.y, y1.z, y1.w};
            #pragma unroll
            for (int i = 0; i < 8; i++)
                #pragma unroll
                for (int j = 0; j < 8; j++)
                    acc[i][j] += ar[i] * br[j];
        }
        if (t + 1 < nk) {
            cur ^= 1;
            As[cur][acol + 0][arow] = a4.x;
            As[cur][acol + 1][arow] = a4.y;
            As[cur][acol + 2][arow] = a4.z;
            As[cur][acol + 3][arow] = a4.w;
            *(float4*)&Bs[cur][brow][bcol] = b4;
            __syncthreads();
        }
    }

    const size_t orow = (size_t)blockIdx.y * 128 + ty * 8;
    const int    ocol = blockIdx.x * 128 + tx * 8;
    #pragma unroll
    for (int i = 0; i < 8; i++) {
        float4 v0 = make_float4(acc[i][0], acc[i][1], acc[i][2], acc[i][3]);
        float4 v1 = make_float4(acc[i][4], acc[i][5], acc[i][6], acc[i][7]);
        *(float4*)&O[(orow + i) * N + ocol]     = v0;
        *(float4*)&O[(orow + i) * N + ocol + 4] = v1;
    }
}

// ---------------------------------------------------------------------------
// sin_emb[f, :] = timing_signal(pos[f]) @ w_pos   (pos[f] = 12 - f)
// ---------------------------------------------------------------------------
__global__ void sinemb_kernel(const float* __restrict__ wpos)
{
    const int f = blockIdx.y;
    const int n = blockIdx.x * 256 + threadIdx.x;
    const float p = (float)(MAXPAST - f);
    const float linc = 9.210340371976184f / 767.0f;  // log(10000)/(num_ts-1)
    float acc = 0.f;
    for (int i = 0; i < 768; i++) {
        float inv = expf(-linc * (float)i);
        float s = p * inv;
        acc += sinf(s) * wpos[(size_t)i * HID + n];
        acc += cosf(s) * wpos[(size_t)(i + 768) * HID + n];
    }
    g_sin[f * HID + n] = acc;
}

// ---------------------------------------------------------------------------
// Attention: one block per (b, u, h). 256 threads.
// rel-shift identity: tb[w][c] = term_bd[w][c-w] on valid band w<=c<=w+12.
// ---------------------------------------------------------------------------
__global__ __launch_bounds__(256) void attn_kernel(
    const unsigned char* __restrict__ mask,
    const float* __restrict__ pds,
    float* __restrict__ out,
    int T)
{
    __shared__ float qs[WW * HD];
    __shared__ float ks[CC * HD];
    __shared__ float vs[CC * HD];
    __shared__ float lg[WW * CC];
    __shared__ float ssc[HD];
    __shared__ int   sval[CC];

    const int u = blockIdx.x, h = blockIdx.y, b = blockIdx.z;
    const int tid = threadIdx.x;

    if (tid < HD) {
        // (D^-0.5 / ln2) * softplus(pds[d])
        const float qsc = 0.0721687836487032f / 0.693147180559945f;
        ssc[tid] = qsc * log1pf(expf(pds[tid]));
    }
    if (tid < CC) {
        int tk = u * WW + tid - MAXPAST;
        sval[tid] = (tk >= 0 && tk < T && mask[(size_t)b * T + tk] == 0);
    }
    __syncthreads();

    for (int i = tid; i < WW * HD; i += 256) {
        int w = i / HD, d = i - w * HD;
        int t = u * WW + w;
        float v = 0.f;
        if (t < T) v = g_q[((size_t)b * T + t) * HID + h * HD + d] * ssc[d];
        qs[i] = v;
    }
    for (int i = tid; i < CC * HD; i += 256) {
        int c = i / HD, d = i - c * HD;
        int t = u * WW + c - MAXPAST;
        if (t >= 0 && t < T) {
            size_t off = ((size_t)b * T + t) * HID + h * HD + d;
            ks[i] = g_k[off];
            vs[i] = g_v[off];
        } else {
            ks[i] = 0.f;
            vs[i] = 0.f;
        }
    }
    __syncthreads();

    // content logits
    for (int idx = tid; idx < WW * CC; idx += 256) {
        int w = idx / CC, c = idx - w * CC;
        const float* qp = qs + w * HD;
        const float* kp = ks + c * HD;
        float acc = 0.f;
        #pragma unroll 8
        for (int d = 0; d < HD; d++) acc += qp[d] * kp[d];
        lg[idx] = acc;
    }
    __syncthreads();

    // position logits, shifted: c = w + f
    for (int idx = tid; idx < WW * FF; idx += 256) {
        int w = idx / FF, f = idx - w * FF;
        const float* qp = qs + w * HD;
        const float* sp = g_sin + (size_t)f * HID + h * HD;
        float acc = 0.f;
        #pragma unroll 8
        for (int d = 0; d < HD; d++) acc += qp[d] * sp[d];
        lg[w * CC + w + f] += acc;
    }
    __syncthreads();

    // tanh cap + mask + softmax (one row per thread)
    if (tid < WW) {
        const int w = tid;
        float row[CC];
        float mx = -FLT_MAX;
        #pragma unroll
        for (int c = 0; c < CC; c++) {
            float lv = tanhf(lg[w * CC + c] * (1.f / 50.f)) * 50.f;
            bool ok = sval[c] && (c >= w) && (c <= w + MAXPAST);
            lv = ok ? lv : -FLT_MAX;
            row[c] = lv;
            if (lv > mx) mx = lv;
        }
        float s = 0.f;
        #pragma unroll
        for (int c = 0; c < CC; c++) {
            float e = (row[c] == -FLT_MAX) ? 0.f : expf(row[c] - mx);
            row[c] = e;
            s += e;
        }
        float inv = 1.f / s;
        #pragma unroll
        for (int c = 0; c < CC; c++) lg[w * CC + c] = row[c] * inv;
    }
    __syncthreads();

    // ctx = probs @ V
    for (int i = tid; i < WW * HD; i += 256) {
        int w = i / HD, d = i - w * HD;
        int t = u * WW + w;
        if (t < T) {
            const float* pp = lg + w * CC;
            float acc = 0.f;
            #pragma unroll
            for (int c = 0; c < CC; c++) acc += pp[c] * vs[c * HD + d];
            out[((size_t)b * T + t) * HID + h * HD + d] = acc;
        }
    }
}

// ---------------------------------------------------------------------------
extern "C" void kernel_launch(void* const* d_in, const int* in_sizes, int n_in,
                              void* d_out, int out_size)
{
    const float*         hs   = (const float*)d_in[0];
    const unsigned char* mask = (const unsigned char*)d_in[1];
    const float*         wq   = (const float*)d_in[2];
    const float*         wk   = (const float*)d_in[3];
    const float*         wv   = (const float*)d_in[4];
    const float*         wpos = (const float*)d_in[5];
    const float*         pds  = (const float*)d_in[6];

    const int M  = in_sizes[0] / HID;   // B*T = 16384
    const int T  = 4096;                // fixed by the problem
    const int Bq = M / T;               // 4
    const int U  = (T + WW - 1) / WW;   // 342

    dim3 gg(HID / 128, M / 128, 3);
    qkv_gemm<<<gg, 256>>>(hs, wq, wk, wv, M, HID, HID);
    sinemb_kernel<<<dim3(HID / 256, FF), 256>>>(wpos);
    attn_kernel<<<dim3(U, NH, Bq), 256>>>(mask, pds, (float*)d_out, T);
}

// round 8
// speedup vs baseline: 2.8691x; 2.8691x over previous
#include <cuda_runtime.h>
#include <cuda_bf16.h>
#include <math.h>
#include <float.h>
#include <stdint.h>

#define HID 1536
#define NH  8
#define HD  192
#define WW  12
#define CC  24
#define FF  13
#define MAXPAST 12

#define BM 128
#define BN 128
#define BK 64
#define NCHUNK (HID / BK)     // 24
#define STG_BYTES 65536       // Ahi 16K | Alo 16K | Bhi 16K | Blo 16K
#define NSTAGE 3
#define KSTR (HD + 1)         // padded K row stride: conflict-free banks

// ---------------- device scratch (no-alloc rule) ----------------
__device__ __align__(128) float g_q[25165824];
__device__ __align__(128) float g_k[25165824];
__device__ __align__(128) float g_v[25165824];
__device__ __align__(128) float g_sin[FF * HID];
__device__ __align__(128) __nv_bfloat16 g_ahi[25165824];
__device__ __align__(128) __nv_bfloat16 g_alo[25165824];
__device__ __align__(128) __nv_bfloat16 g_whi[3 * 2359296];
__device__ __align__(128) __nv_bfloat16 g_wlo[3 * 2359296];

// ---------------- PTX helpers (baseline PTX only) ----------------
__device__ __forceinline__ uint32_t smem_u32(const void* p) {
    uint32_t a;
    asm("{ .reg .u64 t; cvta.to.shared.u64 t, %1; cvt.u32.u64 %0, t; }" : "=r"(a) : "l"(p));
    return a;
}
#define SWZ128(o) ((o) ^ (((o) >> 3) & 0x70))

#define CP_ASYNC16(dst, src) \
    asm volatile("cp.async.cg.shared.global [%0], [%1], 16;" :: "r"(dst), "l"(src))
#define CP_COMMIT()  asm volatile("cp.async.commit_group;")
#define CP_WAIT2()   asm volatile("cp.async.wait_group 2;" ::: "memory")
#define CP_WAIT0()   asm volatile("cp.async.wait_group 0;" ::: "memory")

__device__ __forceinline__ void ldsm4(uint32_t addr, uint32_t* r) {
    asm volatile("ldmatrix.sync.aligned.m8n8.x4.shared.b16 {%0,%1,%2,%3}, [%4];"
                 : "=r"(r[0]), "=r"(r[1]), "=r"(r[2]), "=r"(r[3]) : "r"(addr));
}
__device__ __forceinline__ void mma16816(float* d, const uint32_t* a, const uint32_t* b) {
    asm volatile(
        "mma.sync.aligned.m16n8k16.row.col.f32.bf16.bf16.f32 "
        "{%0,%1,%2,%3}, {%4,%5,%6,%7}, {%8,%9}, {%0,%1,%2,%3};"
        : "+f"(d[0]), "+f"(d[1]), "+f"(d[2]), "+f"(d[3])
        : "r"(a[0]), "r"(a[1]), "r"(a[2]), "r"(a[3]), "r"(b[0]), "r"(b[1]));
}

// ---------------- conversion kernels ----------------
__global__ __launch_bounds__(256) void convA(const float* __restrict__ A) {
    int idx = (blockIdx.x * 256 + threadIdx.x) * 4;
    float4 v = *(const float4*)(A + idx);
    __nv_bfloat16 h[4], l[4];
    float x[4] = {v.x, v.y, v.z, v.w};
    #pragma unroll
    for (int i = 0; i < 4; i++) {
        h[i] = __float2bfloat16(x[i]);
        l[i] = __float2bfloat16(x[i] - __bfloat162float(h[i]));
    }
    *(uint2*)(g_ahi + idx) = *(uint2*)h;
    *(uint2*)(g_alo + idx) = *(uint2*)l;
}

// transpose W [K x N] -> hi/lo [N x K] bf16
__global__ __launch_bounds__(256) void convW(const float* __restrict__ W0,
                                             const float* __restrict__ W1,
                                             const float* __restrict__ W2) {
    __shared__ float ts[32][33];
    const int mat = blockIdx.z;
    const float* Wm = (mat == 0) ? W0 : (mat == 1) ? W1 : W2;
    const int n0 = blockIdx.x * 32, k0 = blockIdx.y * 32;
    const int tx = threadIdx.x & 31, ty = threadIdx.x >> 5;  // 32 x 8
    #pragma unroll
    for (int i = 0; i < 4; i++)
        ts[ty + i * 8][tx] = Wm[(size_t)(k0 + ty + i * 8) * HID + n0 + tx];
    __syncthreads();
    size_t base = (size_t)mat * 2359296;
    #pragma unroll
    for (int i = 0; i < 4; i++) {
        int n = n0 + ty + i * 8, k = k0 + tx;
        float x = ts[tx][ty + i * 8];
        __nv_bfloat16 h = __float2bfloat16(x);
        __nv_bfloat16 l = __float2bfloat16(x - __bfloat162float(h));
        g_whi[base + (size_t)n * HID + k] = h;
        g_wlo[base + (size_t)n * HID + k] = l;
    }
}

// ---------------- HMMA bf16 3-pass GEMM ----------------
__device__ __forceinline__ void load_chunk(
    uint32_t sbase, const __nv_bfloat16* Ah, const __nv_bfloat16* Al,
    const __nv_bfloat16* Bh, const __nv_bfloat16* Bl, int t, int tid)
{
    const int kof = t * BK;
    #pragma unroll
    for (int i = 0; i < 4; i++) {
        int l = tid + i * 256;           // 0..1023
        int row = l >> 3, c16 = l & 7;   // 128 rows x 8 x 16B
        uint32_t so = SWZ128((uint32_t)(row * 128 + c16 * 16));
        size_t go = (size_t)row * HID + kof + c16 * 8;
        CP_ASYNC16(sbase + so,         Ah + go);
        CP_ASYNC16(sbase + 16384 + so, Al + go);
        CP_ASYNC16(sbase + 32768 + so, Bh + go);
        CP_ASYNC16(sbase + 49152 + so, Bl + go);
    }
}

__global__ __launch_bounds__(256, 1) void qkv_mma() {
    extern __shared__ char smem[];
    const uint32_t sb = smem_u32(smem);
    const int tid = threadIdx.x, wid = tid >> 5, lid = tid & 31;
    const int wm = wid >> 1, wn = wid & 1;           // 4 x 2 warp grid
    const int nt = blockIdx.x, mt = blockIdx.y, mat = blockIdx.z;

    const __nv_bfloat16* Ah = g_ahi + (size_t)mt * BM * HID;
    const __nv_bfloat16* Al = g_alo + (size_t)mt * BM * HID;
    const __nv_bfloat16* Bh = g_whi + (size_t)mat * 2359296 + (size_t)nt * BN * HID;
    const __nv_bfloat16* Bl = g_wlo + (size_t)mat * 2359296 + (size_t)nt * BN * HID;
    float* O = (mat == 0) ? g_q : (mat == 1) ? g_k : g_v;

    float acc[2][8][4];
    #pragma unroll
    for (int i = 0; i < 2; i++)
        #pragma unroll
        for (int j = 0; j < 8; j++)
            #pragma unroll
            for (int r = 0; r < 4; r++) acc[i][j][r] = 0.f;

    const int q = lid >> 3, r8 = lid & 7;
    const int a_row = wm * 32 + ((q & 1) << 3) + r8;
    const int a_kb  = (q >> 1) << 4;
    const int b_rowbase = wn * 64 + ((q >> 1) << 3) + r8;
    const int b_kb  = (q & 1) << 4;

    load_chunk(sb,             Ah, Al, Bh, Bl, 0, tid); CP_COMMIT();
    load_chunk(sb + STG_BYTES, Ah, Al, Bh, Bl, 1, tid); CP_COMMIT();

    for (int t = 0; t < NCHUNK; ++t) {
        if (t + 2 < NCHUNK) {
            load_chunk(sb + ((t + 2) % NSTAGE) * STG_BYTES, Ah, Al, Bh, Bl, t + 2, tid);
            CP_COMMIT();
            CP_WAIT2();
        } else {
            CP_WAIT0();
        }
        __syncthreads();
        const uint32_t stg = sb + (t % NSTAGE) * STG_BYTES;

        #pragma unroll
        for (int ks = 0; ks < 4; ++ks) {
            uint32_t ahi[2][4], alo[2][4];
            #pragma unroll
            for (int i = 0; i < 2; i++) {
                uint32_t off = SWZ128((uint32_t)((a_row + i * 16) * 128 + ks * 32 + a_kb));
                ldsm4(stg + off,         ahi[i]);
                ldsm4(stg + 16384 + off, alo[i]);
            }
            #pragma unroll
            for (int j = 0; j < 8; j += 2) {
                uint32_t bh[4], bl[4];
                uint32_t off = SWZ128((uint32_t)((b_rowbase + j * 8) * 128 + ks * 32 + b_kb));
                ldsm4(stg + 32768 + off, bh);
                ldsm4(stg + 49152 + off, bl);
                #pragma unroll
                for (int i = 0; i < 2; i++) {
                    mma16816(acc[i][j],     ahi[i], bh);
                    mma16816(acc[i][j],     alo[i], bh);
                    mma16816(acc[i][j],     ahi[i], bl);
                    mma16816(acc[i][j + 1], ahi[i], bh + 2);
                    mma16816(acc[i][j + 1], alo[i], bh + 2);
                    mma16816(acc[i][j + 1], ahi[i], bl + 2);
                }
            }
        }
        __syncthreads();
    }

    const int orow0 = mt * BM + wm * 32 + (lid >> 2);
    const int ocol0 = nt * BN + wn * 64 + (lid & 3) * 2;
    #pragma unroll
    for (int i = 0; i < 2; i++) {
        #pragma unroll
        for (int j = 0; j < 8; j++) {
            float* p0 = O + (size_t)(orow0 + i * 16)     * HID + ocol0 + j * 8;
            float* p1 = O + (size_t)(orow0 + i * 16 + 8) * HID + ocol0 + j * 8;
            *(float2*)p0 = make_float2(acc[i][j][0], acc[i][j][1]);
            *(float2*)p1 = make_float2(acc[i][j][2], acc[i][j][3]);
        }
    }
}

// ---------------- sin embedding ----------------
__global__ void sinemb_kernel(const float* __restrict__ wpos) {
    const int f = blockIdx.y;
    const int n = blockIdx.x * 256 + threadIdx.x;
    const float p = (float)(MAXPAST - f);
    const float linc = 9.210340371976184f / 767.0f;
    float acc = 0.f;
    for (int i = 0; i < 768; i++) {
        float inv = expf(-linc * (float)i);
        float s = p * inv;
        acc += sinf(s) * wpos[(size_t)i * HID + n];
        acc += cosf(s) * wpos[(size_t)(i + 768) * HID + n];
    }
    g_sin[f * HID + n] = acc;
}

// ---------------- attention: padded K rows, float4 copies ----------------
__global__ __launch_bounds__(256) void attn_kernel(
    const unsigned char* __restrict__ mask,
    const float* __restrict__ pds,
    float* __restrict__ out, int T)
{
    __shared__ float qs[WW * HD];
    __shared__ float ks[CC * KSTR];     // padded: bank-conflict-free Q.K
    __shared__ float vs[CC * HD];
    __shared__ float lg[WW * CC];
    __shared__ float ssc[HD];
    __shared__ int   sval[CC];

    const int u = blockIdx.x, h = blockIdx.y, b = blockIdx.z;
    const int tid = threadIdx.x;

    if (tid < HD) {
        const float qsc = 0.0721687836487032f / 0.693147180559945f;
        ssc[tid] = qsc * log1pf(expf(pds[tid]));
    }
    if (tid < CC) {
        int tk = u * WW + tid - MAXPAST;
        sval[tid] = (tk >= 0 && tk < T && mask[(size_t)b * T + tk] == 0);
    }
    __syncthreads();

    // q: 12 rows x 48 float4
    for (int i = tid; i < WW * (HD / 4); i += 256) {
        int w = i / (HD / 4), dd = i - w * (HD / 4);
        int t = u * WW + w;
        float4 v = make_float4(0.f, 0.f, 0.f, 0.f);
        if (t < T) {
            float4 r = *(const float4*)&g_q[((size_t)b * T + t) * HID + h * HD + dd * 4];
            v = make_float4(r.x * ssc[dd * 4], r.y * ssc[dd * 4 + 1],
                            r.z * ssc[dd * 4 + 2], r.w * ssc[dd * 4 + 3]);
        }
        *(float4*)&qs[w * HD + dd * 4] = v;
    }
    // k (padded store), v: 24 rows x 48 float4
    for (int i = tid; i < CC * (HD / 4); i += 256) {
        int c = i / (HD / 4), dd = i - c * (HD / 4);
        int t = u * WW + c - MAXPAST;
        float4 kv = make_float4(0.f, 0.f, 0.f, 0.f);
        float4 vv = make_float4(0.f, 0.f, 0.f, 0.f);
        if (t >= 0 && t < T) {
            size_t off = ((size_t)b * T + t) * HID + h * HD + dd * 4;
            kv = *(const float4*)&g_k[off];
            vv = *(const float4*)&g_v[off];
        }
        float* kp = &ks[c * KSTR + dd * 4];
        kp[0] = kv.x; kp[1] = kv.y; kp[2] = kv.z; kp[3] = kv.w;
        *(float4*)&vs[c * HD + dd * 4] = vv;
    }
    __syncthreads();

    // content logits (K rows padded -> conflict-free)
    for (int idx = tid; idx < WW * CC; idx += 256) {
        int w = idx / CC, c = idx - w * CC;
        const float* qp = qs + w * HD;
        const float* kp = ks + c * KSTR;
        float acc = 0.f;
        #pragma unroll 8
        for (int d = 0; d < HD; d++) acc = fmaf(qp[d], kp[d], acc);
        lg[idx] = acc;
    }
    __syncthreads();

    // position logits, shifted: c = w + f
    for (int idx = tid; idx < WW * FF; idx += 256) {
        int w = idx / FF, f = idx - w * FF;
        const float* qp = qs + w * HD;
        const float* sp = g_sin + (size_t)f * HID + h * HD;
        float acc = 0.f;
        #pragma unroll 8
        for (int d = 0; d < HD; d++) acc = fmaf(qp[d], sp[d], acc);
        lg[w * CC + w + f] += acc;
    }
    __syncthreads();

    if (tid < WW) {
        const int w = tid;
        float row[CC];
        float mx = -FLT_MAX;
        #pragma unroll
        for (int c = 0; c < CC; c++) {
            float lv = tanhf(lg[w * CC + c] * (1.f / 50.f)) * 50.f;
            bool ok = sval[c] && (c >= w) && (c <= w + MAXPAST);
            lv = ok ? lv : -FLT_MAX;
            row[c] = lv;
            if (lv > mx) mx = lv;
        }
        float s = 0.f;
        #pragma unroll
        for (int c = 0; c < CC; c++) {
            float e = (row[c] == -FLT_MAX) ? 0.f : expf(row[c] - mx);
            row[c] = e; s += e;
        }
        float inv = 1.f / s;
        #pragma unroll
        for (int c = 0; c < CC; c++) lg[w * CC + c] = row[c] * inv;
    }
    __syncthreads();

    // ctx = probs @ V  (lanes vary d -> conflict-free; float4 output)
    for (int i = tid; i < WW * (HD / 4); i += 256) {
        int w = i / (HD / 4), dd = i - w * (HD / 4);
        int t = u * WW + w;
        if (t < T) {
            const float* pp = lg + w * CC;
            float4 a = make_float4(0.f, 0.f, 0.f, 0.f);
            #pragma unroll
            for (int c = 0; c < CC; c++) {
                float p = pp[c];
                const float* vp = &vs[c * HD + dd * 4];
                a.x = fmaf(p, vp[0], a.x);
                a.y = fmaf(p, vp[1], a.y);
                a.z = fmaf(p, vp[2], a.z);
                a.w = fmaf(p, vp[3], a.w);
            }
            *(float4*)&out[((size_t)b * T + t) * HID + h * HD + dd * 4] = a;
        }
    }
}

// ---------------------------------------------------------------------------
extern "C" void kernel_launch(void* const* d_in, const int* in_sizes, int n_in,
                              void* d_out, int out_size)
{
    const float*         hs   = (const float*)d_in[0];
    const unsigned char* mask = (const unsigned char*)d_in[1];
    const float*         wq   = (const float*)d_in[2];
    const float*         wk   = (const float*)d_in[3];
    const float*         wv   = (const float*)d_in[4];
    const float*         wpos = (const float*)d_in[5];
    const float*         pds  = (const float*)d_in[6];

    const int M  = in_sizes[0] / HID;   // 16384
    const int T  = 4096;
    const int Bq = M / T;
    const int U  = (T + WW - 1) / WW;   // 342

    // one-time attribute set (matches the round-3 passing pattern:
    // runs on the pre-capture correctness call, not during capture)
    static int smem_set = 0;
    const int dynsmem = NSTAGE * STG_BYTES;  // 196608
    if (!smem_set) {
        cudaFuncSetAttribute(qkv_mma, cudaFuncAttributeMaxDynamicSharedMemorySize, dynsmem);
        smem_set = 1;
    }

    convA<<<M * HID / 1024, 256>>>(hs);
    convW<<<dim3(HID / 32, HID / 32, 3), 256>>>(wq, wk, wv);
    sinemb_kernel<<<dim3(HID / 256, FF), 256>>>(wpos);
    qkv_mma<<<dim3(HID / BN, M / BM, 3), 256, dynsmem>>>();
    attn_kernel<<<dim3(U, NH, Bq), 256>>>(mask, pds, (float*)d_out, T);
}